// round 4
// baseline (speedup 1.0000x reference)
#include <cuda_runtime.h>
#include <math.h>

// ---------------------------------------------------------------------------
// LOD attention, shapes: B=1, S=2048, D_MODEL=1024, H=16, D=64, G=32,
// WIN=512, TOP1=8. Structural facts: n2=2 and the causal mask over lod2
// blocks force top2_idx == [0,1] always -> candidate lod1 blocks are all of
// 0..63 (ascending) for every query; k_lod2 / v_lod1 / v_lod2 are dead.
// Per-query mask = (local 512 window | top-8 lod1 blocks of 32) & causal.
//
// Precision model (validated by rounds 1/3): reference GEMMs are FULL FP32
// (TF32 emulation made error 5x worse). Remaining mismatch source was RoPE
// transcendentals; here inv_freq/cos/sin are correctly rounded (double
// internally, single fp32 rounding), matching glibc's correctly-rounded
// powf/sinf/cosf that XLA-CPU lowers to. Softmax probs are normalized with
// the global row max/sum (two-pass), as jax.nn.softmax does.
// ---------------------------------------------------------------------------

#define NH    16
#define SEQ   2048
#define HD    64
#define DM    1024
#define NBLK  64          // S / G
#define ATT_SCALE 0.125f  // D^-0.5

// ---- scratch (device globals; no allocation allowed) ----------------------
__device__ float g_q[NH * SEQ * HD];        // (h, s, d), RoPE'd
__device__ float g_k[NH * SEQ * HD];        // (h, s, d), RoPE'd
__device__ float g_v[NH * SEQ * HD];        // (h, s, d)
__device__ float g_k1[NH * NBLK * HD];      // (h, t, d) lod1 block summaries
__device__ unsigned long long g_sel[NH * SEQ]; // per-query top-8 block bitmask
__device__ float g_attn[SEQ * DM];          // (s, h*64+d) pre-O-proj

// ---------------------------------------------------------------------------
// Generic NT SGEMM body: C[m,n] = sum_k A[m,k] * B[n,k], fp32.
// BM=128, BN=64, BK=16, 256 threads, 8x4 per thread.
// ---------------------------------------------------------------------------
__device__ __forceinline__ void gemm_acc(const float* __restrict__ A,
                                         const float* __restrict__ B,
                                         int K, float (&acc)[8][4],
                                         float (*As)[132], float (*Bs)[68],
                                         int m0, int n0, int tid)
{
    const int tm = tid >> 4, tn = tid & 15;
    for (int k0 = 0; k0 < K; k0 += 16) {
#pragma unroll
        for (int i = 0; i < 2; i++) {
            int idx = tid + i * 256;
            int row = idx >> 2, c4 = (idx & 3) * 4;
            float4 va = *(const float4*)(A + (size_t)(m0 + row) * K + k0 + c4);
            As[c4 + 0][row] = va.x; As[c4 + 1][row] = va.y;
            As[c4 + 2][row] = va.z; As[c4 + 3][row] = va.w;
        }
        {
            int row = tid >> 2, c4 = (tid & 3) * 4;
            float4 vb = *(const float4*)(B + (size_t)(n0 + row) * K + k0 + c4);
            Bs[c4 + 0][row] = vb.x; Bs[c4 + 1][row] = vb.y;
            Bs[c4 + 2][row] = vb.z; Bs[c4 + 3][row] = vb.w;
        }
        __syncthreads();
#pragma unroll
        for (int kk = 0; kk < 16; kk++) {
            float4 a0 = *(const float4*)&As[kk][tm * 8];
            float4 a1 = *(const float4*)&As[kk][tm * 8 + 4];
            float4 b  = *(const float4*)&Bs[kk][tn * 4];
            float av[8] = {a0.x, a0.y, a0.z, a0.w, a1.x, a1.y, a1.z, a1.w};
            float bv[4] = {b.x, b.y, b.z, b.w};
#pragma unroll
            for (int i = 0; i < 8; i++)
#pragma unroll
                for (int j = 0; j < 4; j++)
                    acc[i][j] += av[i] * bv[j];
        }
        __syncthreads();
    }
}

// QKV projection: C[s,o] = sum_i x[s,i] * W[o,i]; write into (h,s,d) layout.
__global__ void __launch_bounds__(256) gemm_qkv_kernel(
    const float* __restrict__ x, const float* __restrict__ Wq,
    const float* __restrict__ Wk, const float* __restrict__ Wv)
{
    __shared__ float As[16][132];
    __shared__ float Bs[16][68];
    const float* W = Wq; float* out = g_q;
    if (blockIdx.z == 1)      { W = Wk; out = g_k; }
    else if (blockIdx.z == 2) { W = Wv; out = g_v; }

    float acc[8][4] = {};
    int tid = threadIdx.x;
    int m0 = blockIdx.y * 128, n0 = blockIdx.x * 64;
    gemm_acc(x, W, DM, acc, As, Bs, m0, n0, tid);

    int tm = tid >> 4, tn = tid & 15;
#pragma unroll
    for (int i = 0; i < 8; i++) {
        int s = m0 + tm * 8 + i;
#pragma unroll
        for (int j = 0; j < 4; j++) {
            int o = n0 + tn * 4 + j;
            out[(size_t)(o >> 6) * SEQ * HD + (size_t)s * HD + (o & 63)] = acc[i][j];
        }
    }
}

// O projection: d_out[s,o] = sum_i attn[s,i] * Wo[o,i]
__global__ void __launch_bounds__(256) gemm_o_kernel(
    const float* __restrict__ Wo, float* __restrict__ out)
{
    __shared__ float As[16][132];
    __shared__ float Bs[16][68];
    float acc[8][4] = {};
    int tid = threadIdx.x;
    int m0 = blockIdx.y * 128, n0 = blockIdx.x * 64;
    gemm_acc(g_attn, Wo, DM, acc, As, Bs, m0, n0, tid);

    int tm = tid >> 4, tn = tid & 15;
#pragma unroll
    for (int i = 0; i < 8; i++) {
        int s = m0 + tm * 8 + i;
#pragma unroll
        for (int j = 0; j < 4; j++) {
            int o = n0 + tn * 4 + j;
            out[(size_t)s * DM + o] = acc[i][j];
        }
    }
}

// ---------------------------------------------------------------------------
// RoPE in-place on g_q, g_k. One thread per (h, s, j<32) pair.
// inv_freq computed in double, rounded once to fp32 (== correctly-rounded
// powf); angle = fp32 product (reference semantics); sin/cos via double
// sincos of the fp32 angle, rounded once (== correctly-rounded sinf/cosf).
// ---------------------------------------------------------------------------
__global__ void rope_kernel()
{
    int id = blockIdx.x * blockDim.x + threadIdx.x;
    if (id >= NH * SEQ * 32) return;
    int j = id & 31;
    int s = (id >> 5) & (SEQ - 1);
    int h = id >> 16;

    // inv_freq = 10000^(-j/32), correctly rounded to fp32
    double invd = exp2(-(double)j * 0.41524101186092030); // log2(10000)/32
    float invf = (float)invd;
    float ang = (float)s * invf;          // fp32 product (reference semantics)
    double snd, csd;
    sincos((double)ang, &snd, &csd);
    float sn = (float)snd, cs = (float)csd;

    size_t base = (size_t)h * SEQ * HD + (size_t)s * HD;
    float q1 = g_q[base + j], q2 = g_q[base + j + 32];
    g_q[base + j]      = q1 * cs - q2 * sn;
    g_q[base + j + 32] = q2 * cs + q1 * sn;
    float k1v = g_k[base + j], k2v = g_k[base + j + 32];
    g_k[base + j]      = k1v * cs - k2v * sn;
    g_k[base + j + 32] = k2v * cs + k1v * sn;
}

// ---------------------------------------------------------------------------
// k1[h,t,o] = sum_{i<2048} k[h](t, i) * k_lod1[o, i]   (fp32)
// One block per head; 64x64 output, 4x4 per thread, BK=16.
// ---------------------------------------------------------------------------
__global__ void __launch_bounds__(256) k1_kernel(const float* __restrict__ lod1)
{
    int h = blockIdx.x;
    const float* A = g_k + (size_t)h * SEQ * HD;   // (64, 2048) contiguous
    __shared__ float As[16][68];
    __shared__ float Bs[16][68];
    int tid = threadIdx.x;
    int tm = tid >> 4, tn = tid & 15;
    float acc[4][4] = {};

    for (int k0 = 0; k0 < 2048; k0 += 16) {
        int row = tid >> 2, c4 = (tid & 3) * 4;
        float4 va = *(const float4*)(A + (size_t)row * 2048 + k0 + c4);
        As[c4 + 0][row] = va.x; As[c4 + 1][row] = va.y;
        As[c4 + 2][row] = va.z; As[c4 + 3][row] = va.w;
        float4 vb = *(const float4*)(lod1 + (size_t)row * 2048 + k0 + c4);
        Bs[c4 + 0][row] = vb.x; Bs[c4 + 1][row] = vb.y;
        Bs[c4 + 2][row] = vb.z; Bs[c4 + 3][row] = vb.w;
        __syncthreads();
#pragma unroll
        for (int kk = 0; kk < 16; kk++) {
            float4 a = *(const float4*)&As[kk][tm * 4];
            float4 b = *(const float4*)&Bs[kk][tn * 4];
            float av[4] = {a.x, a.y, a.z, a.w};
            float bv[4] = {b.x, b.y, b.z, b.w};
#pragma unroll
            for (int i = 0; i < 4; i++)
#pragma unroll
                for (int j = 0; j < 4; j++)
                    acc[i][j] += av[i] * bv[j];
        }
        __syncthreads();
    }
#pragma unroll
    for (int i = 0; i < 4; i++)
#pragma unroll
        for (int j = 0; j < 4; j++)
            g_k1[(size_t)h * 4096 + (size_t)(tm * 4 + i) * 64 + tn * 4 + j] = acc[i][j];
}

// ---------------------------------------------------------------------------
// Selection: per (h, s) compute 64 block scores q . k1[h,t] (fp32),
// take top-8 (value desc, index asc on ties) -> 64-bit mask.
// Block: 256 threads = 8 warps, one query per warp; k1[h] staged in smem.
// ---------------------------------------------------------------------------
__global__ void __launch_bounds__(256) select_kernel()
{
    int h = blockIdx.y;
    __shared__ float k1s[64 * 65];
    int tid = threadIdx.x;
    for (int i = tid; i < 64 * 64; i += 256) {
        int t = i >> 6, d = i & 63;
        k1s[t * 65 + d] = g_k1[(size_t)h * 4096 + i];
    }
    __syncthreads();

    int w = tid >> 5, lane = tid & 31;
    int s = blockIdx.x * 8 + w;
    const float* qp = g_q + (size_t)h * SEQ * HD + (size_t)s * HD;
    float2 qpair = *(const float2*)(qp + 2 * lane);

    float a0 = 0.f, a1 = 0.f;
#pragma unroll
    for (int d = 0; d < 64; d++) {
        float qd = __shfl_sync(0xffffffffu, (d & 1) ? qpair.y : qpair.x, d >> 1);
        a0 += qd * k1s[lane * 65 + d];
        a1 += qd * k1s[(lane + 32) * 65 + d];
    }

    int i0 = lane, i1 = lane + 32;
    unsigned long long msk = 0ull;
#pragma unroll
    for (int it = 0; it < 8; it++) {
        float bv; int bi;
        if (a0 > a1 || (a0 == a1 && i0 < i1)) { bv = a0; bi = i0; }
        else                                  { bv = a1; bi = i1; }
#pragma unroll
        for (int off = 16; off; off >>= 1) {
            float ov = __shfl_xor_sync(0xffffffffu, bv, off);
            int   oi = __shfl_xor_sync(0xffffffffu, bi, off);
            if (ov > bv || (ov == bv && oi < bi)) { bv = ov; bi = oi; }
        }
        msk |= 1ull << bi;
        if (bi == i0) a0 = -INFINITY;
        if (bi == i1) a1 = -INFINITY;
    }
    if (lane == 0) g_sel[(size_t)h * SEQ + s] = msk;
}

// ---------------------------------------------------------------------------
// Masked attention, TWO-PASS (reference normalizes with the global row
// max/sum, like jax.nn.softmax):
//   pass A: (m, l) over needed key tiles (scores only)
//   pass B: prob = exp(s - m) / l, then PV
// One block per (head, 32-query tile); key tiles of 32 skipped when neither
// the local window nor any query's top-8 mask needs them.
// Thread layout: 256 threads, r = tid>>3 (query row), c = tid&7.
//   scores : thread computes 4 keys j = c*4 + jj
//   PV     : thread accumulates 8 dims d = c*8 + dd
// ---------------------------------------------------------------------------
__global__ void __launch_bounds__(256) attn_kernel()
{
    int h = blockIdx.y, qt = blockIdx.x;
    int s0 = qt * 32;

    __shared__ float qs[32 * 68];
    __shared__ float ks[32 * 68];
    __shared__ float vs[32 * 68];
    __shared__ float ps[32 * 36];
    __shared__ unsigned long long msk[32];
    __shared__ unsigned long long s_union;

    int tid = threadIdx.x;
    const size_t hbase = (size_t)h * SEQ * HD;

    // load Q tile
#pragma unroll
    for (int i = 0; i < 2; i++) {
        int idx = tid + i * 256;
        int r = idx >> 4, c4 = (idx & 15) * 4;
        *(float4*)&qs[r * 68 + c4] =
            *(const float4*)(g_q + hbase + (size_t)(s0 + r) * HD + c4);
    }
    if (tid < 32) {
        unsigned long long m = g_sel[(size_t)h * SEQ + s0 + tid];
        msk[tid] = m;
        unsigned int lo = (unsigned int)m, hi = (unsigned int)(m >> 32);
#pragma unroll
        for (int off = 16; off; off >>= 1) {
            lo |= __shfl_xor_sync(0xffffffffu, lo, off);
            hi |= __shfl_xor_sync(0xffffffffu, hi, off);
        }
        if (tid == 0) s_union = ((unsigned long long)hi << 32) | lo;
    }
    __syncthreads();

    const int r = tid >> 3, c = tid & 7;
    const int jbase = c * 4, dbase = c * 8;
    const int s = s0 + r;
    const unsigned long long mr = msk[r];
    const unsigned long long uni = s_union;

    // ---------------- pass A: row max + normalizer ----------------
    float m_i = -1e30f, l_i = 0.f;
    for (int t = 0; t <= qt; t++) {
        bool need = (t * 32 + 31 >= s0 - 511) || ((uni >> t) & 1ull);
        if (!need) continue;

        __syncthreads();
#pragma unroll
        for (int i = 0; i < 2; i++) {
            int idx = tid + i * 256;
            int rr = idx >> 4, c4 = (idx & 15) * 4;
            *(float4*)&ks[rr * 68 + c4] =
                *(const float4*)(g_k + hbase + (size_t)(t * 32 + rr) * HD + c4);
        }
        __syncthreads();

        float sc[4] = {};
#pragma unroll
        for (int d4 = 0; d4 < 64; d4 += 4) {
            float4 qv = *(const float4*)&qs[r * 68 + d4];
#pragma unroll
            for (int jj = 0; jj < 4; jj++) {
                float4 kv = *(const float4*)&ks[(jbase + jj) * 68 + d4];
                sc[jj] += qv.x * kv.x + qv.y * kv.y + qv.z * kv.z + qv.w * kv.w;
            }
        }
        bool selt = (mr >> t) & 1ull;
#pragma unroll
        for (int jj = 0; jj < 4; jj++) {
            int key = t * 32 + jbase + jj;
            bool ok = (key <= s) && (key >= s - 511 || selt);
            sc[jj] = ok ? sc[jj] * ATT_SCALE : -1e30f;
        }

        float rmax = fmaxf(fmaxf(sc[0], sc[1]), fmaxf(sc[2], sc[3]));
#pragma unroll
        for (int off = 1; off < 8; off <<= 1)
            rmax = fmaxf(rmax, __shfl_xor_sync(0xffffffffu, rmax, off));
        float mnew = fmaxf(m_i, rmax);
        float rs = 0.f;
#pragma unroll
        for (int jj = 0; jj < 4; jj++) rs += __expf(sc[jj] - mnew);
#pragma unroll
        for (int off = 1; off < 8; off <<= 1)
            rs += __shfl_xor_sync(0xffffffffu, rs, off);
        l_i = l_i * __expf(m_i - mnew) + rs;
        m_i = mnew;
    }
    const float inv_l = 1.0f / l_i;   // every row has its diagonal key

    // ---------------- pass B: normalized probs, PV ----------------
    float accv[8] = {};
    for (int t = 0; t <= qt; t++) {
        bool need = (t * 32 + 31 >= s0 - 511) || ((uni >> t) & 1ull);
        if (!need) continue;

        __syncthreads();
#pragma unroll
        for (int i = 0; i < 2; i++) {
            int idx = tid + i * 256;
            int rr = idx >> 4, c4 = (idx & 15) * 4;
            size_t goff = hbase + (size_t)(t * 32 + rr) * HD + c4;
            *(float4*)&ks[rr * 68 + c4] = *(const float4*)(g_k + goff);
            *(float4*)&vs[rr * 68 + c4] = *(const float4*)(g_v + goff);
        }
        __syncthreads();

        float sc[4] = {};
#pragma unroll
        for (int d4 = 0; d4 < 64; d4 += 4) {
            float4 qv = *(const float4*)&qs[r * 68 + d4];
#pragma unroll
            for (int jj = 0; jj < 4; jj++) {
                float4 kv = *(const float4*)&ks[(jbase + jj) * 68 + d4];
                sc[jj] += qv.x * kv.x + qv.y * kv.y + qv.z * kv.z + qv.w * kv.w;
            }
        }
        bool selt = (mr >> t) & 1ull;
#pragma unroll
        for (int jj = 0; jj < 4; jj++) {
            int key = t * 32 + jbase + jj;
            bool ok = (key <= s) && (key >= s - 511 || selt);
            sc[jj] = ok ? sc[jj] * ATT_SCALE : -1e30f;
            ps[r * 36 + jbase + jj] = __expf(sc[jj] - m_i) * inv_l;
        }
        __syncwarp();   // ps row r produced & consumed within one warp

#pragma unroll 4
        for (int j = 0; j < 32; j++) {
            float pj = ps[r * 36 + j];
            float4 v0 = *(const float4*)&vs[j * 68 + dbase];
            float4 v1 = *(const float4*)&vs[j * 68 + dbase + 4];
            accv[0] += pj * v0.x; accv[1] += pj * v0.y;
            accv[2] += pj * v0.z; accv[3] += pj * v0.w;
            accv[4] += pj * v1.x; accv[5] += pj * v1.y;
            accv[6] += pj * v1.z; accv[7] += pj * v1.w;
        }
    }

    size_t obase = (size_t)s * DM + (size_t)h * HD + dbase;
    *(float4*)&g_attn[obase]     = make_float4(accv[0], accv[1], accv[2], accv[3]);
    *(float4*)&g_attn[obase + 4] = make_float4(accv[4], accv[5], accv[6], accv[7]);
}

// ---------------------------------------------------------------------------
extern "C" void kernel_launch(void* const* d_in, const int* in_sizes, int n_in,
                              void* d_out, int out_size)
{
    (void)in_sizes; (void)n_in; (void)out_size;
    const float* x    = (const float*)d_in[0];
    const float* W_q  = (const float*)d_in[1];
    const float* W_k  = (const float*)d_in[2];
    const float* W_v  = (const float*)d_in[3];
    const float* W_o  = (const float*)d_in[4];
    const float* lod1 = (const float*)d_in[5];
    // d_in[6..8] (v_lod1, k_lod2, v_lod2) are dead for these shapes.
    float* out = (float*)d_out;

    gemm_qkv_kernel<<<dim3(DM / 64, SEQ / 128, 3), 256>>>(x, W_q, W_k, W_v);
    rope_kernel<<<(NH * SEQ * 32) / 256, 256>>>();
    k1_kernel<<<NH, 256>>>(lod1);
    select_kernel<<<dim3(SEQ / 8, NH), 256>>>();
    attn_kernel<<<dim3(SEQ / 32, NH), 256>>>();
    gemm_o_kernel<<<dim3(DM / 64, SEQ / 128, 1), 256>>>(W_o, out);
}

// round 5
// speedup vs baseline: 3.3569x; 3.3569x over previous
#include <cuda_runtime.h>
#include <math.h>

// ---------------------------------------------------------------------------
// LOD attention, B=1, S=2048, D_MODEL=1024, H=16, D=64, G=32, WIN=512, TOP1=8.
// Structural: top2 stage is identity for these shapes -> candidate lod1 blocks
// are all 0..63; mask = (local 512 window | top-8 lod1 blocks) & causal.
// Precision (validated R1/R3/R4): full fp32 GEMMs, correctly-rounded RoPE
// transcendentals, fp32 softmax. rel_err 1.19e-6 with this model.
// ---------------------------------------------------------------------------

#define NH    16
#define SEQ   2048
#define HD    64
#define DM    1024
#define NBLK  64
#define ATT_SCALE 0.125f

// ---- scratch ---------------------------------------------------------------
__device__ float g_q[NH * SEQ * HD];
__device__ float g_k[NH * SEQ * HD];
__device__ float g_v[NH * SEQ * HD];
__device__ float g_k1[NH * NBLK * HD];
__device__ unsigned long long g_sel[NH * SEQ];
__device__ float g_attn[SEQ * DM];
__device__ float g_cs[SEQ * 32];
__device__ float g_sn[SEQ * 32];

// ---------------------------------------------------------------------------
// 128x128x(K=1024) NT SGEMM body, BK=8, double-buffered, 8x8 per thread.
// C[m,n] = sum_k A[m,k] * B[n,k].  256 threads.
// Warp-tiled mapping: warp w (0..7) -> (wm=w&3, wn=w>>2); lane l ->
// tm = wm*32 + (l&3)*8, tn = wn*64 + (l>>2)*8.  Conflict-free LDS reads.
// ---------------------------------------------------------------------------
__device__ __forceinline__ void sgemm_tile(const float* __restrict__ A,
                                           const float* __restrict__ B,
                                           float (&acc)[8][8],
                                           int m0, int n0,
                                           float* As, float* Bs)   // each 2*8*132
{
    const int tid  = threadIdx.x;
    const int lrow = tid >> 1;
    const int lcol = (tid & 1) * 4;
    const float* aptr = A + (size_t)(m0 + lrow) * DM + lcol;
    const float* bptr = B + (size_t)(n0 + lrow) * DM + lcol;

    const int w = tid >> 5, l = tid & 31;
    const int tm = (w & 3) * 32 + (l & 3) * 8;
    const int tn = (w >> 2) * 64 + (l >> 2) * 8;

    {
        float4 a = *(const float4*)aptr;
        float4 b = *(const float4*)bptr;
        As[(lcol + 0) * 132 + lrow] = a.x; As[(lcol + 1) * 132 + lrow] = a.y;
        As[(lcol + 2) * 132 + lrow] = a.z; As[(lcol + 3) * 132 + lrow] = a.w;
        Bs[(lcol + 0) * 132 + lrow] = b.x; Bs[(lcol + 1) * 132 + lrow] = b.y;
        Bs[(lcol + 2) * 132 + lrow] = b.z; Bs[(lcol + 3) * 132 + lrow] = b.w;
    }
    __syncthreads();

    const int NK = DM / 8;   // 128
    for (int kt = 0; kt < NK; kt++) {
        const float* Ac = As + (kt & 1) * (8 * 132);
        const float* Bc = Bs + (kt & 1) * (8 * 132);
        float4 an, bn;
        bool pre = (kt + 1 < NK);
        if (pre) {
            an = *(const float4*)(aptr + (kt + 1) * 8);
            bn = *(const float4*)(bptr + (kt + 1) * 8);
        }
#pragma unroll
        for (int kk = 0; kk < 8; kk++) {
            float4 a0 = *(const float4*)&Ac[kk * 132 + tm];
            float4 a1 = *(const float4*)&Ac[kk * 132 + tm + 4];
            float4 b0 = *(const float4*)&Bc[kk * 132 + tn];
            float4 b1 = *(const float4*)&Bc[kk * 132 + tn + 4];
            float av[8] = {a0.x, a0.y, a0.z, a0.w, a1.x, a1.y, a1.z, a1.w};
            float bv[8] = {b0.x, b0.y, b0.z, b0.w, b1.x, b1.y, b1.z, b1.w};
#pragma unroll
            for (int i = 0; i < 8; i++)
#pragma unroll
                for (int j = 0; j < 8; j++)
                    acc[i][j] += av[i] * bv[j];
        }
        if (pre) {
            float* An = As + ((kt + 1) & 1) * (8 * 132);
            float* Bn = Bs + ((kt + 1) & 1) * (8 * 132);
            An[(lcol + 0) * 132 + lrow] = an.x; An[(lcol + 1) * 132 + lrow] = an.y;
            An[(lcol + 2) * 132 + lrow] = an.z; An[(lcol + 3) * 132 + lrow] = an.w;
            Bn[(lcol + 0) * 132 + lrow] = bn.x; Bn[(lcol + 1) * 132 + lrow] = bn.y;
            Bn[(lcol + 2) * 132 + lrow] = bn.z; Bn[(lcol + 3) * 132 + lrow] = bn.w;
            __syncthreads();
        }
    }
}

// QKV projection -> (h,s,d) layout.
__global__ void __launch_bounds__(256) gemm_qkv_kernel(
    const float* __restrict__ x, const float* __restrict__ Wq,
    const float* __restrict__ Wk, const float* __restrict__ Wv)
{
    __shared__ float As[2 * 8 * 132];
    __shared__ float Bs[2 * 8 * 132];
    const float* W = Wq; float* out = g_q;
    if (blockIdx.z == 1)      { W = Wk; out = g_k; }
    else if (blockIdx.z == 2) { W = Wv; out = g_v; }

    float acc[8][8] = {};
    int m0 = blockIdx.y * 128, n0 = blockIdx.x * 128;
    sgemm_tile(x, W, acc, m0, n0, As, Bs);

    const int w = threadIdx.x >> 5, l = threadIdx.x & 31;
    const int tm = (w & 3) * 32 + (l & 3) * 8;
    const int tn = (w >> 2) * 64 + (l >> 2) * 8;
    int o0 = n0 + tn;                       // 8-aligned, stays in one head
    float* obase = out + (size_t)(o0 >> 6) * SEQ * HD + (o0 & 63);
#pragma unroll
    for (int i = 0; i < 8; i++) {
        int s = m0 + tm + i;
        *(float4*)(obase + (size_t)s * HD)     = make_float4(acc[i][0], acc[i][1], acc[i][2], acc[i][3]);
        *(float4*)(obase + (size_t)s * HD + 4) = make_float4(acc[i][4], acc[i][5], acc[i][6], acc[i][7]);
    }
}

// O projection -> d_out row-major.
__global__ void __launch_bounds__(256) gemm_o_kernel(
    const float* __restrict__ Wo, float* __restrict__ out)
{
    __shared__ float As[2 * 8 * 132];
    __shared__ float Bs[2 * 8 * 132];
    float acc[8][8] = {};
    int m0 = blockIdx.y * 128, n0 = blockIdx.x * 128;
    sgemm_tile(g_attn, Wo, acc, m0, n0, As, Bs);

    const int w = threadIdx.x >> 5, l = threadIdx.x & 31;
    const int tm = (w & 3) * 32 + (l & 3) * 8;
    const int tn = (w >> 2) * 64 + (l >> 2) * 8;
#pragma unroll
    for (int i = 0; i < 8; i++) {
        int s = m0 + tm + i;
        *(float4*)(out + (size_t)s * DM + n0 + tn)     = make_float4(acc[i][0], acc[i][1], acc[i][2], acc[i][3]);
        *(float4*)(out + (size_t)s * DM + n0 + tn + 4) = make_float4(acc[i][4], acc[i][5], acc[i][6], acc[i][7]);
    }
}

// ---------------------------------------------------------------------------
// RoPE: (s,j) table (correctly-rounded via double), then cheap apply.
// ---------------------------------------------------------------------------
__global__ void rope_tab_kernel()
{
    int id = blockIdx.x * blockDim.x + threadIdx.x;   // SEQ*32
    if (id >= SEQ * 32) return;
    int j = id & 31, s = id >> 5;
    double invd = exp2(-(double)j * 0.41524101186092030);  // log2(10000)/32
    float ang = (float)s * (float)invd;                    // fp32 product
    double snd, csd;
    sincos((double)ang, &snd, &csd);
    g_cs[id] = (float)csd;
    g_sn[id] = (float)snd;
}

__global__ void rope_apply_kernel()
{
    int id = blockIdx.x * blockDim.x + threadIdx.x;   // NH*SEQ*32
    if (id >= NH * SEQ * 32) return;
    int j = id & 31;
    int s = (id >> 5) & (SEQ - 1);
    int h = id >> 16;
    float cs = g_cs[(s << 5) + j], sn = g_sn[(s << 5) + j];

    size_t base = (size_t)h * SEQ * HD + (size_t)s * HD;
    float q1 = g_q[base + j], q2 = g_q[base + j + 32];
    g_q[base + j]      = q1 * cs - q2 * sn;
    g_q[base + j + 32] = q2 * cs + q1 * sn;
    float k1v = g_k[base + j], k2v = g_k[base + j + 32];
    g_k[base + j]      = k1v * cs - k2v * sn;
    g_k[base + j + 32] = k2v * cs + k1v * sn;
}

// ---------------------------------------------------------------------------
// k1[h,t,o] = sum_i k[h](t,i) * k_lod1[o,i]   (64x64x2048 per head)
// ---------------------------------------------------------------------------
__global__ void __launch_bounds__(256) k1_kernel(const float* __restrict__ lod1)
{
    int h = blockIdx.x;
    const float* A = g_k + (size_t)h * SEQ * HD;
    __shared__ float As[16][68];
    __shared__ float Bs[16][68];
    int tid = threadIdx.x;
    int tm = tid >> 4, tn = tid & 15;
    float acc[4][4] = {};

    for (int k0 = 0; k0 < 2048; k0 += 16) {
        int row = tid >> 2, c4 = (tid & 3) * 4;
        float4 va = *(const float4*)(A + (size_t)row * 2048 + k0 + c4);
        As[c4 + 0][row] = va.x; As[c4 + 1][row] = va.y;
        As[c4 + 2][row] = va.z; As[c4 + 3][row] = va.w;
        float4 vb = *(const float4*)(lod1 + (size_t)row * 2048 + k0 + c4);
        Bs[c4 + 0][row] = vb.x; Bs[c4 + 1][row] = vb.y;
        Bs[c4 + 2][row] = vb.z; Bs[c4 + 3][row] = vb.w;
        __syncthreads();
#pragma unroll
        for (int kk = 0; kk < 16; kk++) {
            float4 a = *(const float4*)&As[kk][tm * 4];
            float4 b = *(const float4*)&Bs[kk][tn * 4];
            float av[4] = {a.x, a.y, a.z, a.w};
            float bv[4] = {b.x, b.y, b.z, b.w};
#pragma unroll
            for (int i = 0; i < 4; i++)
#pragma unroll
                for (int j = 0; j < 4; j++)
                    acc[i][j] += av[i] * bv[j];
        }
        __syncthreads();
    }
#pragma unroll
    for (int i = 0; i < 4; i++)
#pragma unroll
        for (int j = 0; j < 4; j++)
            g_k1[(size_t)h * 4096 + (size_t)(tm * 4 + i) * 64 + tn * 4 + j] = acc[i][j];
}

// ---------------------------------------------------------------------------
// Top-8 block selection -> 64-bit mask per (h, s).
// ---------------------------------------------------------------------------
__global__ void __launch_bounds__(256) select_kernel()
{
    int h = blockIdx.y;
    __shared__ float k1s[64 * 65];
    int tid = threadIdx.x;
    for (int i = tid; i < 64 * 64; i += 256) {
        int t = i >> 6, d = i & 63;
        k1s[t * 65 + d] = g_k1[(size_t)h * 4096 + i];
    }
    __syncthreads();

    int w = tid >> 5, lane = tid & 31;
    int s = blockIdx.x * 8 + w;
    const float* qp = g_q + (size_t)h * SEQ * HD + (size_t)s * HD;
    float2 qpair = *(const float2*)(qp + 2 * lane);

    float a0 = 0.f, a1 = 0.f;
#pragma unroll
    for (int d = 0; d < 64; d++) {
        float qd = __shfl_sync(0xffffffffu, (d & 1) ? qpair.y : qpair.x, d >> 1);
        a0 += qd * k1s[lane * 65 + d];
        a1 += qd * k1s[(lane + 32) * 65 + d];
    }

    int i0 = lane, i1 = lane + 32;
    unsigned long long msk = 0ull;
#pragma unroll
    for (int it = 0; it < 8; it++) {
        float bv; int bi;
        if (a0 > a1 || (a0 == a1 && i0 < i1)) { bv = a0; bi = i0; }
        else                                  { bv = a1; bi = i1; }
#pragma unroll
        for (int off = 16; off; off >>= 1) {
            float ov = __shfl_xor_sync(0xffffffffu, bv, off);
            int   oi = __shfl_xor_sync(0xffffffffu, bi, off);
            if (ov > bv || (ov == bv && oi < bi)) { bv = ov; bi = oi; }
        }
        msk |= 1ull << bi;
        if (bi == i0) a0 = -INFINITY;
        if (bi == i1) a1 = -INFINITY;
    }
    if (lane == 0) g_sel[(size_t)h * SEQ + s] = msk;
}

// ---------------------------------------------------------------------------
// Single-pass flash attention with online softmax.
// Block = (head, 32-query tile), key tiles of 64 (= 2 selection blocks),
// skipped when neither the window nor the union mask needs them.
// 256 threads: warp wr (0..7) owns rows r = wr*4+i; lane tc owns keys
// {tc, tc+32} for QK and dims {2tc, 2tc+1} for PV.
// Dynamic smem: qs[32][68] ks[64][68] vs[64][68] ps[64][36] msk[33].
// ---------------------------------------------------------------------------
#define ATTN_SMEM_BYTES ((32*68 + 64*68 + 64*68 + 64*36) * 4 + 33 * 8)

__global__ void __launch_bounds__(256) attn_kernel()
{
    extern __shared__ float sm[];
    float* qs = sm;                      // 32*68
    float* ks = qs + 32 * 68;            // 64*68
    float* vs = ks + 64 * 68;            // 64*68
    float* ps = vs + 64 * 68;            // 64*36  (ps[j][r])
    unsigned long long* msk = (unsigned long long*)(ps + 64 * 36); // [33]

    int h = blockIdx.y, qt = blockIdx.x;
    int s0 = qt * 32;
    int tid = threadIdx.x;
    const size_t hbase = (size_t)h * SEQ * HD;

#pragma unroll
    for (int i = 0; i < 2; i++) {
        int idx = tid + i * 256;
        int r = idx >> 4, c4 = (idx & 15) * 4;
        *(float4*)&qs[r * 68 + c4] =
            *(const float4*)(g_q + hbase + (size_t)(s0 + r) * HD + c4);
    }
    if (tid < 32) {
        unsigned long long m = g_sel[(size_t)h * SEQ + s0 + tid];
        msk[tid] = m;
        unsigned lo = (unsigned)m, hi = (unsigned)(m >> 32);
#pragma unroll
        for (int off = 16; off; off >>= 1) {
            lo |= __shfl_xor_sync(0xffffffffu, lo, off);
            hi |= __shfl_xor_sync(0xffffffffu, hi, off);
        }
        if (tid == 0) msk[32] = ((unsigned long long)hi << 32) | lo;
    }
    __syncthreads();

    const int wr = tid >> 5, tc = tid & 31;
    const unsigned long long uni = msk[32];
    unsigned long long mrow[4];
#pragma unroll
    for (int i = 0; i < 4; i++) mrow[i] = msk[wr * 4 + i];

    float m_i[4] = {-1e30f, -1e30f, -1e30f, -1e30f};
    float l_i[4] = {};
    float acc[4][2] = {};

    const int ktmax = (s0 + 31) >> 6;
    for (int kt = 0; kt <= ktmax; kt++) {
        bool need = (kt * 64 + 63 >= s0 - 511) || (((uni >> (2 * kt)) & 3ull) != 0);
        if (!need) continue;

        __syncthreads();   // previous tile's PV done with vs
#pragma unroll
        for (int i = 0; i < 4; i++) {
            int idx = tid + i * 256;
            int rr = idx >> 4, c4 = (idx & 15) * 4;
            size_t goff = hbase + (size_t)(kt * 64 + rr) * HD + c4;
            *(float4*)&ks[rr * 68 + c4] = *(const float4*)(g_k + goff);
            *(float4*)&vs[rr * 68 + c4] = *(const float4*)(g_v + goff);
        }
        __syncthreads();

        // ---- scores: 4 rows x 2 keys, float4 dot over d ----
        float sc[4][2] = {};
#pragma unroll
        for (int d4 = 0; d4 < 64; d4 += 4) {
            float4 k0 = *(const float4*)&ks[tc * 68 + d4];
            float4 k1 = *(const float4*)&ks[(tc + 32) * 68 + d4];
#pragma unroll
            for (int i = 0; i < 4; i++) {
                float4 qv = *(const float4*)&qs[(wr * 4 + i) * 68 + d4];
                sc[i][0] += qv.x * k0.x + qv.y * k0.y + qv.z * k0.z + qv.w * k0.w;
                sc[i][1] += qv.x * k1.x + qv.y * k1.y + qv.z * k1.z + qv.w * k1.w;
            }
        }

        // ---- mask + online softmax per row ----
        float pst[4][2];
#pragma unroll
        for (int i = 0; i < 4; i++) {
            int s = s0 + wr * 4 + i;
#pragma unroll
            for (int jj = 0; jj < 2; jj++) {
                int key = kt * 64 + tc + 32 * jj;
                bool sel = (mrow[i] >> (2 * kt + jj)) & 1ull;
                bool ok = (key <= s) && (key >= s - 511 || sel);
                sc[i][jj] = ok ? sc[i][jj] * ATT_SCALE : -1e30f;
            }
            float rmax = fmaxf(sc[i][0], sc[i][1]);
#pragma unroll
            for (int off = 16; off; off >>= 1)
                rmax = fmaxf(rmax, __shfl_xor_sync(0xffffffffu, rmax, off));
            float mnew = fmaxf(m_i[i], rmax);
            float p0 = __expf(sc[i][0] - mnew);
            float p1 = __expf(sc[i][1] - mnew);
            float rs = p0 + p1;
#pragma unroll
            for (int off = 16; off; off >>= 1)
                rs += __shfl_xor_sync(0xffffffffu, rs, off);
            float f = __expf(m_i[i] - mnew);
            l_i[i] = l_i[i] * f + rs;
            m_i[i] = mnew;
            acc[i][0] *= f; acc[i][1] *= f;
            pst[i][0] = p0; pst[i][1] = p1;
        }
        // ps[j][r]: two float4 stores (rows wr*4..+3 for keys tc, tc+32)
        *(float4*)&ps[tc * 36 + wr * 4] =
            make_float4(pst[0][0], pst[1][0], pst[2][0], pst[3][0]);
        *(float4*)&ps[(tc + 32) * 36 + wr * 4] =
            make_float4(pst[0][1], pst[1][1], pst[2][1], pst[3][1]);
        __syncwarp();   // ps for this warp's rows written/read within warp

        // ---- PV: dims d = 2tc, 2tc+1 ----
#pragma unroll 8
        for (int j = 0; j < 64; j++) {
            float4 pj = *(const float4*)&ps[j * 36 + wr * 4];   // broadcast
            float2 vj = *(const float2*)&vs[j * 68 + tc * 2];
            acc[0][0] += pj.x * vj.x; acc[0][1] += pj.x * vj.y;
            acc[1][0] += pj.y * vj.x; acc[1][1] += pj.y * vj.y;
            acc[2][0] += pj.z * vj.x; acc[2][1] += pj.z * vj.y;
            acc[3][0] += pj.w * vj.x; acc[3][1] += pj.w * vj.y;
        }
    }

#pragma unroll
    for (int i = 0; i < 4; i++) {
        int s = s0 + wr * 4 + i;
        float inv = 1.0f / l_i[i];       // diagonal key always present
        *(float2*)&g_attn[(size_t)s * DM + h * HD + tc * 2] =
            make_float2(acc[i][0] * inv, acc[i][1] * inv);
    }
}

// ---------------------------------------------------------------------------
extern "C" void kernel_launch(void* const* d_in, const int* in_sizes, int n_in,
                              void* d_out, int out_size)
{
    (void)in_sizes; (void)n_in; (void)out_size;
    const float* x    = (const float*)d_in[0];
    const float* W_q  = (const float*)d_in[1];
    const float* W_k  = (const float*)d_in[2];
    const float* W_v  = (const float*)d_in[3];
    const float* W_o  = (const float*)d_in[4];
    const float* lod1 = (const float*)d_in[5];
    float* out = (float*)d_out;

    static int smem_set = 0;
    if (!smem_set) {
        cudaFuncSetAttribute(attn_kernel,
                             cudaFuncAttributeMaxDynamicSharedMemorySize,
                             ATTN_SMEM_BYTES);
        smem_set = 1;
    }

    rope_tab_kernel<<<(SEQ * 32) / 256, 256>>>();
    gemm_qkv_kernel<<<dim3(DM / 128, SEQ / 128, 3), 256>>>(x, W_q, W_k, W_v);
    rope_apply_kernel<<<(NH * SEQ * 32) / 256, 256>>>();
    k1_kernel<<<NH, 256>>>(lod1);
    select_kernel<<<dim3(SEQ / 8, NH), 256>>>();
    attn_kernel<<<dim3(SEQ / 32, NH), 256, ATTN_SMEM_BYTES>>>();
    gemm_o_kernel<<<dim3(DM / 128, SEQ / 128, 1), 256>>>(W_o, out);
}

// round 8
// speedup vs baseline: 4.2508x; 1.2663x over previous
#include <cuda_runtime.h>
#include <math.h>
#include <stdint.h>

// ---------------------------------------------------------------------------
// LOD attention, B=1, S=2048, D_MODEL=1024, H=16, D=64, G=32, WIN=512, TOP1=8.
// Structural: top2 stage is identity -> candidate lod1 blocks are all 0..63;
// mask = (local 512 window | top-8 lod1 blocks) & causal.
// Toolchain fact (R7): ptxas target is sm_100 (family) -> NO tcgen05.
// Tensor path used instead: mma.sync m16n8k8 tf32 (sm_80+ baseline PTX) with
// 3xTF32 emulation (hi/lo split, Ah*Bh + Ah*Bl + Al*Bh, fp32 accumulate),
// preserving the validated full-fp32 precision model (~1e-6 end-to-end).
// ---------------------------------------------------------------------------

#define NH    16
#define SEQ   2048
#define HD    64
#define DM    1024
#define NBLK  64
#define ATT_SCALE 0.125f

// ---- scratch ---------------------------------------------------------------
__device__ float g_q[NH * SEQ * HD];
__device__ float g_k[NH * SEQ * HD];
__device__ float g_v[NH * SEQ * HD];
__device__ float g_k1[NH * NBLK * HD];
__device__ float g_k1p[8 * NH * NBLK * HD];
__device__ unsigned long long g_sel[NH * SEQ];
__device__ float g_attn[SEQ * DM];
__device__ float g_cs[SEQ * 32];
__device__ float g_sn[SEQ * 32];

__device__ __forceinline__ float tf32r(float x) {
    unsigned r;
    asm("cvt.rna.tf32.f32 %0, %1;" : "=r"(r) : "f"(x));
    return __uint_as_float(r);
}

__device__ __forceinline__ void mma_tf32_16x8x8(float* c, const uint32_t* a,
                                                uint32_t b0, uint32_t b1)
{
    asm volatile(
        "mma.sync.aligned.m16n8k8.row.col.f32.tf32.tf32.f32 "
        "{%0,%1,%2,%3}, {%4,%5,%6,%7}, {%8,%9}, {%0,%1,%2,%3};"
        : "+f"(c[0]), "+f"(c[1]), "+f"(c[2]), "+f"(c[3])
        : "r"(a[0]), "r"(a[1]), "r"(a[2]), "r"(a[3]), "r"(b0), "r"(b1));
}

// ---------------------------------------------------------------------------
// 3xTF32 mma.sync GEMM: C[128x128] per CTA, C[m,n] = sum_k A[m,k]*B[n,k],
// K = 1024, BK = 16, double-buffered smem of pre-split tf32 hi/lo tiles.
// 256 threads = 8 warps; warp w -> (wm = (w&1)*64, wn = (w>>1)*32);
// warp tile 64x32 = 4 m16-tiles x 4 n8-tiles.
// Smem per buffer: As_hi, As_lo, Bs_hi, Bs_lo each [128][17] f32.
// ---------------------------------------------------------------------------
#define TSTR   17
#define TILE_F (128 * TSTR)
#define GEMM_SMEM_BYTES (2 * 4 * TILE_F * 4)

__global__ void __launch_bounds__(256, 1) mma_gemm_kernel(
    const float* __restrict__ x,
    const float* __restrict__ Wq, const float* __restrict__ Wk,
    const float* __restrict__ Wv, const float* __restrict__ Wo,
    float* __restrict__ out_o, int is_o)
{
    extern __shared__ float sm[];
    const int tid = threadIdx.x;
    const int w = tid >> 5, lane = tid & 31;
    const int g = lane >> 2, tg = lane & 3;
    const int wm = (w & 1) * 64, wn = (w >> 1) * 32;

    const float* A;
    const float* B;
    float* outp = 0;
    if (is_o) { A = g_attn; B = Wo; }
    else {
        A = x;
        int z = blockIdx.z;
        if (z == 0)      { B = Wq; outp = g_q; }
        else if (z == 1) { B = Wk; outp = g_k; }
        else             { B = Wv; outp = g_v; }
    }
    const int m0 = blockIdx.y * 128, n0 = blockIdx.x * 128;
    const float* Asrc = A + (size_t)m0 * DM;
    const float* Bsrc = B + (size_t)n0 * DM;

    // staging indices: thread covers (row, c4) for f = tid and tid+256
    const int row0 = tid >> 2,        c40 = (tid & 3) * 4;
    const int row1 = (tid + 256) >> 2, c41 = ((tid + 256) & 3) * 4;

    float acc[4][4][4] = {};

#define STAGE_SPLIT(buf, va, vb, r, c)                                        \
    do {                                                                      \
        float* Ah_ = sm + (buf) * 4 * TILE_F;                                 \
        float* Al_ = Ah_ + TILE_F;                                            \
        float* Bh_ = Al_ + TILE_F;                                            \
        float* Bl_ = Bh_ + TILE_F;                                            \
        float h;                                                              \
        h = tf32r((va).x); Ah_[(r)*TSTR+(c)+0] = h; Al_[(r)*TSTR+(c)+0] = tf32r((va).x - h); \
        h = tf32r((va).y); Ah_[(r)*TSTR+(c)+1] = h; Al_[(r)*TSTR+(c)+1] = tf32r((va).y - h); \
        h = tf32r((va).z); Ah_[(r)*TSTR+(c)+2] = h; Al_[(r)*TSTR+(c)+2] = tf32r((va).z - h); \
        h = tf32r((va).w); Ah_[(r)*TSTR+(c)+3] = h; Al_[(r)*TSTR+(c)+3] = tf32r((va).w - h); \
        h = tf32r((vb).x); Bh_[(r)*TSTR+(c)+0] = h; Bl_[(r)*TSTR+(c)+0] = tf32r((vb).x - h); \
        h = tf32r((vb).y); Bh_[(r)*TSTR+(c)+1] = h; Bl_[(r)*TSTR+(c)+1] = tf32r((vb).y - h); \
        h = tf32r((vb).z); Bh_[(r)*TSTR+(c)+2] = h; Bl_[(r)*TSTR+(c)+2] = tf32r((vb).z - h); \
        h = tf32r((vb).w); Bh_[(r)*TSTR+(c)+3] = h; Bl_[(r)*TSTR+(c)+3] = tf32r((vb).w - h); \
    } while (0)

    // prologue: stage chunk 0 into buffer 0
    {
        float4 a0 = *(const float4*)(Asrc + (size_t)row0 * DM + c40);
        float4 b0 = *(const float4*)(Bsrc + (size_t)row0 * DM + c40);
        float4 a1 = *(const float4*)(Asrc + (size_t)row1 * DM + c41);
        float4 b1 = *(const float4*)(Bsrc + (size_t)row1 * DM + c41);
        STAGE_SPLIT(0, a0, b0, row0, c40);
        STAGE_SPLIT(0, a1, b1, row1, c41);
    }
    __syncthreads();

    const int NKC = DM / 16;   // 64 chunks
    for (int kc = 0; kc < NKC; kc++) {
        const int b = kc & 1;
        float4 pa0, pb0, pa1, pb1;
        const bool pre = (kc + 1 < NKC);
        if (pre) {
            int k0 = (kc + 1) * 16;
            pa0 = *(const float4*)(Asrc + (size_t)row0 * DM + k0 + c40);
            pb0 = *(const float4*)(Bsrc + (size_t)row0 * DM + k0 + c40);
            pa1 = *(const float4*)(Asrc + (size_t)row1 * DM + k0 + c41);
            pb1 = *(const float4*)(Bsrc + (size_t)row1 * DM + k0 + c41);
        }

        const uint32_t* Ah = (const uint32_t*)(sm + b * 4 * TILE_F);
        const uint32_t* Al = Ah + TILE_F;
        const uint32_t* Bh = Al + TILE_F;
        const uint32_t* Bl = Bh + TILE_F;

#pragma unroll
        for (int s = 0; s < 2; s++) {
            const int kk = s * 8;
            uint32_t ah[4][4], al[4][4];
#pragma unroll
            for (int i = 0; i < 4; i++) {
                int r = wm + i * 16 + g;
                ah[i][0] = Ah[r * TSTR + kk + tg];
                ah[i][1] = Ah[(r + 8) * TSTR + kk + tg];
                ah[i][2] = Ah[r * TSTR + kk + tg + 4];
                ah[i][3] = Ah[(r + 8) * TSTR + kk + tg + 4];
                al[i][0] = Al[r * TSTR + kk + tg];
                al[i][1] = Al[(r + 8) * TSTR + kk + tg];
                al[i][2] = Al[r * TSTR + kk + tg + 4];
                al[i][3] = Al[(r + 8) * TSTR + kk + tg + 4];
            }
#pragma unroll
            for (int j = 0; j < 4; j++) {
                int n = wn + j * 8 + g;
                uint32_t bh0 = Bh[n * TSTR + kk + tg];
                uint32_t bh1 = Bh[n * TSTR + kk + tg + 4];
                uint32_t bl0 = Bl[n * TSTR + kk + tg];
                uint32_t bl1 = Bl[n * TSTR + kk + tg + 4];
#pragma unroll
                for (int i = 0; i < 4; i++) {
                    mma_tf32_16x8x8(acc[i][j], ah[i], bh0, bh1);
                    mma_tf32_16x8x8(acc[i][j], ah[i], bl0, bl1);
                    mma_tf32_16x8x8(acc[i][j], al[i], bh0, bh1);
                }
            }
        }

        if (pre) {
            __syncthreads();   // all warps done reading buffer b^1
            STAGE_SPLIT(b ^ 1, pa0, pb0, row0, c40);
            STAGE_SPLIT(b ^ 1, pa1, pb1, row1, c41);
            __syncthreads();
        }
    }

    // epilogue
#pragma unroll
    for (int i = 0; i < 4; i++) {
        int r0 = m0 + wm + i * 16 + g;
#pragma unroll
        for (int j = 0; j < 4; j++) {
            int col = n0 + wn + j * 8 + tg * 2;
            if (!is_o) {
                int head = col >> 6, d = col & 63;
                float* ob = outp + (size_t)head * SEQ * HD + d;
                *(float2*)(ob + (size_t)r0 * HD)       = make_float2(acc[i][j][0], acc[i][j][1]);
                *(float2*)(ob + (size_t)(r0 + 8) * HD) = make_float2(acc[i][j][2], acc[i][j][3]);
            } else {
                *(float2*)(out_o + (size_t)r0 * DM + col)       = make_float2(acc[i][j][0], acc[i][j][1]);
                *(float2*)(out_o + (size_t)(r0 + 8) * DM + col) = make_float2(acc[i][j][2], acc[i][j][3]);
            }
        }
    }
#undef STAGE_SPLIT
}

// ---------------------------------------------------------------------------
// RoPE: (s,j) table (correctly-rounded via double), then cheap apply.
// ---------------------------------------------------------------------------
__global__ void rope_tab_kernel()
{
    int id = blockIdx.x * blockDim.x + threadIdx.x;
    if (id >= SEQ * 32) return;
    int j = id & 31, s = id >> 5;
    double invd = exp2(-(double)j * 0.41524101186092030);  // log2(10000)/32
    float ang = (float)s * (float)invd;
    double snd, csd;
    sincos((double)ang, &snd, &csd);
    g_cs[id] = (float)csd;
    g_sn[id] = (float)snd;
}

__global__ void rope_apply_kernel()
{
    int id = blockIdx.x * blockDim.x + threadIdx.x;
    if (id >= NH * SEQ * 32) return;
    int j = id & 31;
    int s = (id >> 5) & (SEQ - 1);
    int h = id >> 16;
    float cs = g_cs[(s << 5) + j], sn = g_sn[(s << 5) + j];

    size_t base = (size_t)h * SEQ * HD + (size_t)s * HD;
    float q1 = g_q[base + j], q2 = g_q[base + j + 32];
    g_q[base + j]      = q1 * cs - q2 * sn;
    g_q[base + j + 32] = q2 * cs + q1 * sn;
    float k1v = g_k[base + j], k2v = g_k[base + j + 32];
    g_k[base + j]      = k1v * cs - k2v * sn;
    g_k[base + j + 32] = k2v * cs + k1v * sn;
}

// ---------------------------------------------------------------------------
// k1 split-K: phase 1 partials (16 heads x 8 splits), phase 2 ordered reduce.
// ---------------------------------------------------------------------------
__global__ void __launch_bounds__(256) k1_part_kernel(const float* __restrict__ lod1)
{
    int h = blockIdx.x, sp = blockIdx.y;
    const float* A = g_k + (size_t)h * SEQ * HD;
    __shared__ float As[16][68];
    __shared__ float Bs[16][68];
    int tid = threadIdx.x;
    int tm = tid >> 4, tn = tid & 15;
    float acc[4][4] = {};

    int kbeg = sp * 256, kend = kbeg + 256;
    for (int k0 = kbeg; k0 < kend; k0 += 16) {
        int row = tid >> 2, c4 = (tid & 3) * 4;
        float4 va = *(const float4*)(A + (size_t)row * 2048 + k0 + c4);
        As[c4 + 0][row] = va.x; As[c4 + 1][row] = va.y;
        As[c4 + 2][row] = va.z; As[c4 + 3][row] = va.w;
        float4 vb = *(const float4*)(lod1 + (size_t)row * 2048 + k0 + c4);
        Bs[c4 + 0][row] = vb.x; Bs[c4 + 1][row] = vb.y;
        Bs[c4 + 2][row] = vb.z; Bs[c4 + 3][row] = vb.w;
        __syncthreads();
#pragma unroll
        for (int kk = 0; kk < 16; kk++) {
            float4 a = *(const float4*)&As[kk][tm * 4];
            float4 b = *(const float4*)&Bs[kk][tn * 4];
            float av[4] = {a.x, a.y, a.z, a.w};
            float bv[4] = {b.x, b.y, b.z, b.w};
#pragma unroll
            for (int i = 0; i < 4; i++)
#pragma unroll
                for (int j = 0; j < 4; j++)
                    acc[i][j] += av[i] * bv[j];
        }
        __syncthreads();
    }
    float* outp = g_k1p + ((size_t)sp * NH + h) * 4096;
#pragma unroll
    for (int i = 0; i < 4; i++)
#pragma unroll
        for (int j = 0; j < 4; j++)
            outp[(size_t)(tm * 4 + i) * 64 + tn * 4 + j] = acc[i][j];
}

__global__ void k1_reduce_kernel()
{
    int i = blockIdx.x * blockDim.x + threadIdx.x;
    if (i >= NH * 4096) return;
    float s = 0.f;
#pragma unroll
    for (int sp = 0; sp < 8; sp++)
        s += g_k1p[(size_t)sp * NH * 4096 + i];
    g_k1[i] = s;
}

// ---------------------------------------------------------------------------
// Top-8 block selection -> 64-bit mask per (h, s).
// ---------------------------------------------------------------------------
__global__ void __launch_bounds__(256) select_kernel()
{
    int h = blockIdx.y;
    __shared__ float k1s[64 * 65];
    int tid = threadIdx.x;
    for (int i = tid; i < 64 * 64; i += 256) {
        int t = i >> 6, d = i & 63;
        k1s[t * 65 + d] = g_k1[(size_t)h * 4096 + i];
    }
    __syncthreads();

    int w = tid >> 5, lane = tid & 31;
    int s = blockIdx.x * 8 + w;
    const float* qp = g_q + (size_t)h * SEQ * HD + (size_t)s * HD;
    float2 qpair = *(const float2*)(qp + 2 * lane);

    float a0 = 0.f, a1 = 0.f;
#pragma unroll
    for (int d = 0; d < 64; d++) {
        float qd = __shfl_sync(0xffffffffu, (d & 1) ? qpair.y : qpair.x, d >> 1);
        a0 += qd * k1s[lane * 65 + d];
        a1 += qd * k1s[(lane + 32) * 65 + d];
    }

    int i0 = lane, i1 = lane + 32;
    unsigned long long msk = 0ull;
#pragma unroll
    for (int it = 0; it < 8; it++) {
        float bv; int bi;
        if (a0 > a1 || (a0 == a1 && i0 < i1)) { bv = a0; bi = i0; }
        else                                  { bv = a1; bi = i1; }
#pragma unroll
        for (int off = 16; off; off >>= 1) {
            float ov = __shfl_xor_sync(0xffffffffu, bv, off);
            int   oi = __shfl_xor_sync(0xffffffffu, bi, off);
            if (ov > bv || (ov == bv && oi < bi)) { bv = ov; bi = oi; }
        }
        msk |= 1ull << bi;
        if (bi == i0) a0 = -INFINITY;
        if (bi == i1) a1 = -INFINITY;
    }
    if (lane == 0) g_sel[(size_t)h * SEQ + s] = msk;
}

// ---------------------------------------------------------------------------
// Single-pass flash attention with online softmax (R5, passing).
// ---------------------------------------------------------------------------
#define ATTN_SMEM_BYTES ((32*68 + 64*68 + 64*68 + 64*36) * 4 + 33 * 8)

__global__ void __launch_bounds__(256) attn_kernel()
{
    extern __shared__ float smf[];
    float* qs = smf;                     // 32*68
    float* ks = qs + 32 * 68;            // 64*68
    float* vs = ks + 64 * 68;            // 64*68
    float* ps = vs + 64 * 68;            // 64*36  (ps[j][r])
    unsigned long long* msk = (unsigned long long*)(ps + 64 * 36); // [33]

    int h = blockIdx.y, qt = blockIdx.x;
    int s0 = qt * 32;
    int tid = threadIdx.x;
    const size_t hbase = (size_t)h * SEQ * HD;

#pragma unroll
    for (int i = 0; i < 2; i++) {
        int idx = tid + i * 256;
        int r = idx >> 4, c4 = (idx & 15) * 4;
        *(float4*)&qs[r * 68 + c4] =
            *(const float4*)(g_q + hbase + (size_t)(s0 + r) * HD + c4);
    }
    if (tid < 32) {
        unsigned long long m = g_sel[(size_t)h * SEQ + s0 + tid];
        msk[tid] = m;
        unsigned lo = (unsigned)m, hi = (unsigned)(m >> 32);
#pragma unroll
        for (int off = 16; off; off >>= 1) {
            lo |= __shfl_xor_sync(0xffffffffu, lo, off);
            hi |= __shfl_xor_sync(0xffffffffu, hi, off);
        }
        if (tid == 0) msk[32] = ((unsigned long long)hi << 32) | lo;
    }
    __syncthreads();

    const int wr = tid >> 5, tc = tid & 31;
    const unsigned long long uni = msk[32];
    unsigned long long mrow[4];
#pragma unroll
    for (int i = 0; i < 4; i++) mrow[i] = msk[wr * 4 + i];

    float m_i[4] = {-1e30f, -1e30f, -1e30f, -1e30f};
    float l_i[4] = {};
    float acc[4][2] = {};

    const int ktmax = (s0 + 31) >> 6;
    for (int kt = 0; kt <= ktmax; kt++) {
        bool need = (kt * 64 + 63 >= s0 - 511) || (((uni >> (2 * kt)) & 3ull) != 0);
        if (!need) continue;

        __syncthreads();
#pragma unroll
        for (int i = 0; i < 4; i++) {
            int idx = tid + i * 256;
            int rr = idx >> 4, c4 = (idx & 15) * 4;
            size_t goff = hbase + (size_t)(kt * 64 + rr) * HD + c4;
            *(float4*)&ks[rr * 68 + c4] = *(const float4*)(g_k + goff);
            *(float4*)&vs[rr * 68 + c4] = *(const float4*)(g_v + goff);
        }
        __syncthreads();

        float sc[4][2] = {};
#pragma unroll
        for (int d4 = 0; d4 < 64; d4 += 4) {
            float4 k0 = *(const float4*)&ks[tc * 68 + d4];
            float4 k1 = *(const float4*)&ks[(tc + 32) * 68 + d4];
#pragma unroll
            for (int i = 0; i < 4; i++) {
                float4 qv = *(const float4*)&qs[(wr * 4 + i) * 68 + d4];
                sc[i][0] += qv.x * k0.x + qv.y * k0.y + qv.z * k0.z + qv.w * k0.w;
                sc[i][1] += qv.x * k1.x + qv.y * k1.y + qv.z * k1.z + qv.w * k1.w;
            }
        }

        float pst[4][2];
#pragma unroll
        for (int i = 0; i < 4; i++) {
            int s = s0 + wr * 4 + i;
#pragma unroll
            for (int jj = 0; jj < 2; jj++) {
                int key = kt * 64 + tc + 32 * jj;
                bool sel = (mrow[i] >> (2 * kt + jj)) & 1ull;
                bool ok = (key <= s) && (key >= s - 511 || sel);
                sc[i][jj] = ok ? sc[i][jj] * ATT_SCALE : -1e30f;
            }
            float rmax = fmaxf(sc[i][0], sc[i][1]);
#pragma unroll
            for (int off = 16; off; off >>= 1)
                rmax = fmaxf(rmax, __shfl_xor_sync(0xffffffffu, rmax, off));
            float mnew = fmaxf(m_i[i], rmax);
            float p0 = __expf(sc[i][0] - mnew);
            float p1 = __expf(sc[i][1] - mnew);
            float rs = p0 + p1;
#pragma unroll
            for (int off = 16; off; off >>= 1)
                rs += __shfl_xor_sync(0xffffffffu, rs, off);
            float f = __expf(m_i[i] - mnew);
            l_i[i] = l_i[i] * f + rs;
            m_i[i] = mnew;
            acc[i][0] *= f; acc[i][1] *= f;
            pst[i][0] = p0; pst[i][1] = p1;
        }
        *(float4*)&ps[tc * 36 + wr * 4] =
            make_float4(pst[0][0], pst[1][0], pst[2][0], pst[3][0]);
        *(float4*)&ps[(tc + 32) * 36 + wr * 4] =
            make_float4(pst[0][1], pst[1][1], pst[2][1], pst[3][1]);
        __syncwarp();

#pragma unroll 8
        for (int j = 0; j < 64; j++) {
            float4 pj = *(const float4*)&ps[j * 36 + wr * 4];
            float2 vj = *(const float2*)&vs[j * 68 + tc * 2];
            acc[0][0] += pj.x * vj.x; acc[0][1] += pj.x * vj.y;
            acc[1][0] += pj.y * vj.x; acc[1][1] += pj.y * vj.y;
            acc[2][0] += pj.z * vj.x; acc[2][1] += pj.z * vj.y;
            acc[3][0] += pj.w * vj.x; acc[3][1] += pj.w * vj.y;
        }
    }

#pragma unroll
    for (int i = 0; i < 4; i++) {
        int s = s0 + wr * 4 + i;
        float inv = 1.0f / l_i[i];
        *(float2*)&g_attn[(size_t)s * DM + h * HD + tc * 2] =
            make_float2(acc[i][0] * inv, acc[i][1] * inv);
    }
}

// ---------------------------------------------------------------------------
extern "C" void kernel_launch(void* const* d_in, const int* in_sizes, int n_in,
                              void* d_out, int out_size)
{
    (void)in_sizes; (void)n_in; (void)out_size;
    const float* x    = (const float*)d_in[0];
    const float* W_q  = (const float*)d_in[1];
    const float* W_k  = (const float*)d_in[2];
    const float* W_v  = (const float*)d_in[3];
    const float* W_o  = (const float*)d_in[4];
    const float* lod1 = (const float*)d_in[5];
    float* out = (float*)d_out;

    static int attr_set = 0;
    if (!attr_set) {
        cudaFuncSetAttribute(attn_kernel,
                             cudaFuncAttributeMaxDynamicSharedMemorySize,
                             ATTN_SMEM_BYTES);
        cudaFuncSetAttribute(mma_gemm_kernel,
                             cudaFuncAttributeMaxDynamicSharedMemorySize,
                             GEMM_SMEM_BYTES);
        attr_set = 1;
    }

    rope_tab_kernel<<<(SEQ * 32) / 256, 256>>>();
    mma_gemm_kernel<<<dim3(DM / 128, SEQ / 128, 3), 256, GEMM_SMEM_BYTES>>>(
        x, W_q, W_k, W_v, nullptr, nullptr, 0);
    rope_apply_kernel<<<(NH * SEQ * 32) / 256, 256>>>();
    k1_part_kernel<<<dim3(NH, 8), 256>>>(lod1);
    k1_reduce_kernel<<<(NH * 4096) / 256, 256>>>();
    select_kernel<<<dim3(SEQ / 8, NH), 256>>>();
    attn_kernel<<<dim3(SEQ / 32, NH), 256, ATTN_SMEM_BYTES>>>();
    mma_gemm_kernel<<<dim3(DM / 128, SEQ / 128, 1), 256, GEMM_SMEM_BYTES>>>(
        nullptr, nullptr, nullptr, nullptr, W_o, out, 1);
}

// round 11
// speedup vs baseline: 4.3185x; 1.0159x over previous
#include <cuda_runtime.h>
#include <math.h>
#include <stdint.h>

// ---------------------------------------------------------------------------
// LOD attention, B=1, S=2048, D_MODEL=1024, H=16, D=64, G=32, WIN=512, TOP1=8.
// Structural: top2 stage is identity -> candidate lod1 blocks are all 0..63;
// mask = (local 512 window | top-8 lod1 blocks) & causal.
//
// Precision: fp32-class GEMMs required (R8: 3xTF32 noise flipped a top-8
// selection -> 9.8e-4). bf16x6 fp32 emulation on mma.sync m16n8k16 —
// x = h+m+l (exact 3x bf16 split, in-tile), products hh+hm+mh+mm+hl+lh;
// dropped terms ~2^-24 (~fp32 rounding). No gmem presplit, no fat register
// preloads (R9 lesson: 128MiB local-mem growth tripped the alloc guard).
// R10 was a broker flake (same signature as R6); design resubmitted.
// ---------------------------------------------------------------------------

#define NH    16
#define SEQ   2048
#define HD    64
#define DM    1024
#define NBLK  64
#define ATT_SCALE 0.125f

// ---- scratch ---------------------------------------------------------------
__device__ float g_q[NH * SEQ * HD];
__device__ float g_k[NH * SEQ * HD];
__device__ float g_v[NH * SEQ * HD];
__device__ float g_k1[NH * NBLK * HD];
__device__ float g_k1p[8 * NH * NBLK * HD];
__device__ unsigned long long g_sel[NH * SEQ];
__device__ float g_attn[SEQ * DM];
__device__ float g_cs[SEQ * 32];
__device__ float g_sn[SEQ * 32];

// ---- helpers ---------------------------------------------------------------
__device__ __forceinline__ uint32_t bf16r(float x) {   // rne bf16 bit pattern
    uint32_t u = __float_as_uint(x);
    return (u + 0x7FFFu + ((u >> 16) & 1u)) >> 16;
}
__device__ __forceinline__ float bf2f(uint32_t b) {
    return __uint_as_float(b << 16);
}
__device__ __forceinline__ void mma_bf16(float* c, const uint32_t* a,
                                         uint32_t b0, uint32_t b1)
{
    asm volatile(
        "mma.sync.aligned.m16n8k16.row.col.f32.bf16.bf16.f32 "
        "{%0,%1,%2,%3}, {%4,%5,%6,%7}, {%8,%9}, {%0,%1,%2,%3};"
        : "+f"(c[0]), "+f"(c[1]), "+f"(c[2]), "+f"(c[3])
        : "r"(a[0]), "r"(a[1]), "r"(a[2]), "r"(a[3]), "r"(b0), "r"(b1));
}

// ---------------------------------------------------------------------------
// bf16x6 GEMM: C[128x128] per CTA, C[m,n] = sum_k A[m,k]*B[n,k], K=1024.
// BK=16, double-buffered smem of in-tile-split bf16 h/m/l tiles
// (pairs packed: tile = [128 rows][8 u32 used, stride 12]).
// 256 threads = 8 warps; warp w -> (wm=(w&1)*64, wn=(w>>1)*32);
// warp tile 64x32 = 4 m16 x 4 n8 tiles; 6 mma (k16) per tile per chunk.
// ---------------------------------------------------------------------------
#define TROW 12
#define TILE_U (128 * TROW)
#define GEMM_SMEM_BYTES (2 * 6 * TILE_U * 4)
#define SMT(buf, mat, spl) (((buf) * 6 + (mat) * 3 + (spl)) * TILE_U)

__device__ __forceinline__ void split_store8(uint32_t* su, int toff_h,
                                             const float* f, int soff)
{
    uint32_t ph[4], pm[4], pl[4];
#pragma unroll
    for (int c = 0; c < 4; c++) {
        float f0 = f[2 * c], f1 = f[2 * c + 1];
        uint32_t h0 = bf16r(f0); float r0 = f0 - bf2f(h0);
        uint32_t m0 = bf16r(r0); uint32_t l0 = bf16r(r0 - bf2f(m0));
        uint32_t h1 = bf16r(f1); float r1 = f1 - bf2f(h1);
        uint32_t m1 = bf16r(r1); uint32_t l1 = bf16r(r1 - bf2f(m1));
        ph[c] = h0 | (h1 << 16);
        pm[c] = m0 | (m1 << 16);
        pl[c] = l0 | (l1 << 16);
    }
#pragma unroll
    for (int c = 0; c < 4; c++) {
        su[toff_h + soff + c]              = ph[c];
        su[toff_h + TILE_U + soff + c]     = pm[c];
        su[toff_h + 2 * TILE_U + soff + c] = pl[c];
    }
}

__global__ void __launch_bounds__(256, 1) bf16x6_gemm_kernel(
    const float* __restrict__ x,
    const float* __restrict__ Wq, const float* __restrict__ Wk,
    const float* __restrict__ Wv, const float* __restrict__ Wo,
    float* __restrict__ out_o, int is_o)
{
    extern __shared__ uint32_t su[];
    const int tid = threadIdx.x;
    const int w = tid >> 5, lane = tid & 31;
    const int g = lane >> 2, tg = lane & 3;
    const int wm = (w & 1) * 64, wn = (w >> 1) * 32;

    const float* A;
    const float* B;
    float* outp = 0;
    if (is_o) { A = g_attn; B = Wo; }
    else {
        A = x;
        int z = blockIdx.z;
        if (z == 0)      { B = Wq; outp = g_q; }
        else if (z == 1) { B = Wk; outp = g_k; }
        else             { B = Wv; outp = g_v; }
    }
    const int m0 = blockIdx.y * 128, n0 = blockIdx.x * 128;

    // staging: thread covers row r = tid>>1, cols half*8 .. +7
    const int r = tid >> 1, half = tid & 1;
    const int soff = r * TROW + half * 4;
    const float* aptr = A + (size_t)(m0 + r) * DM + half * 8;
    const float* bptr = B + (size_t)(n0 + r) * DM + half * 8;

    float acc[4][4][4] = {};

    // prologue: chunk 0 -> buffer 0
    {
        float fa[8], fb[8];
        *(float4*)fa       = *(const float4*)aptr;
        *(float4*)(fa + 4) = *(const float4*)(aptr + 4);
        *(float4*)fb       = *(const float4*)bptr;
        *(float4*)(fb + 4) = *(const float4*)(bptr + 4);
        split_store8(su, SMT(0, 0, 0), fa, soff);
        split_store8(su, SMT(0, 1, 0), fb, soff);
    }
    __syncthreads();

    const int NKC = DM / 16;   // 64
    for (int kc = 0; kc < NKC; kc++) {
        const int b = kc & 1;
        float fa[8], fb[8];
        const bool pre = (kc + 1 < NKC);
        if (pre) {
            int k0 = (kc + 1) * 16;
            *(float4*)fa       = *(const float4*)(aptr + k0);
            *(float4*)(fa + 4) = *(const float4*)(aptr + k0 + 4);
            *(float4*)fb       = *(const float4*)(bptr + k0);
            *(float4*)(fb + 4) = *(const float4*)(bptr + k0 + 4);
        }

        // compute: for each a-split s, b-splits t with s + t <= 2
#pragma unroll
        for (int s = 0; s < 3; s++) {
            const uint32_t* As = su + SMT(b, 0, s);
            uint32_t af[4][4];
#pragma unroll
            for (int i = 0; i < 4; i++) {
                int r0 = wm + i * 16 + g;
                af[i][0] = As[r0 * TROW + tg];
                af[i][1] = As[(r0 + 8) * TROW + tg];
                af[i][2] = As[r0 * TROW + tg + 4];
                af[i][3] = As[(r0 + 8) * TROW + tg + 4];
            }
#pragma unroll
            for (int t = 0; t < 3; t++) {
                if (t < 3 - s) {
                    const uint32_t* Bs = su + SMT(b, 1, t);
#pragma unroll
                    for (int j = 0; j < 4; j++) {
                        int n = wn + j * 8 + g;
                        uint32_t b0 = Bs[n * TROW + tg];
                        uint32_t b1 = Bs[n * TROW + tg + 4];
#pragma unroll
                        for (int i = 0; i < 4; i++)
                            mma_bf16(acc[i][j], af[i], b0, b1);
                    }
                }
            }
        }

        if (pre) {
            __syncthreads();   // everyone done reading buffer b^1
            split_store8(su, SMT(b ^ 1, 0, 0), fa, soff);
            split_store8(su, SMT(b ^ 1, 1, 0), fb, soff);
            __syncthreads();
        }
    }

    // epilogue: c0,c1 = row g cols 2tg,2tg+1; c2,c3 = row g+8
#pragma unroll
    for (int i = 0; i < 4; i++) {
        int r0 = m0 + wm + i * 16 + g;
#pragma unroll
        for (int j = 0; j < 4; j++) {
            int col = n0 + wn + j * 8 + tg * 2;
            if (!is_o) {
                int head = col >> 6, d = col & 63;
                float* ob = outp + (size_t)head * SEQ * HD + d;
                *(float2*)(ob + (size_t)r0 * HD)       = make_float2(acc[i][j][0], acc[i][j][1]);
                *(float2*)(ob + (size_t)(r0 + 8) * HD) = make_float2(acc[i][j][2], acc[i][j][3]);
            } else {
                *(float2*)(out_o + (size_t)r0 * DM + col)       = make_float2(acc[i][j][0], acc[i][j][1]);
                *(float2*)(out_o + (size_t)(r0 + 8) * DM + col) = make_float2(acc[i][j][2], acc[i][j][3]);
            }
        }
    }
}

// ---------------------------------------------------------------------------
// RoPE: (s,j) table (correctly-rounded via double), then cheap apply.
// ---------------------------------------------------------------------------
__global__ void rope_tab_kernel()
{
    int id = blockIdx.x * blockDim.x + threadIdx.x;
    if (id >= SEQ * 32) return;
    int j = id & 31, s = id >> 5;
    double invd = exp2(-(double)j * 0.41524101186092030);  // log2(10000)/32
    float ang = (float)s * (float)invd;
    double snd, csd;
    sincos((double)ang, &snd, &csd);
    g_cs[id] = (float)csd;
    g_sn[id] = (float)snd;
}

__global__ void rope_apply_kernel()
{
    int id = blockIdx.x * blockDim.x + threadIdx.x;
    if (id >= NH * SEQ * 32) return;
    int j = id & 31;
    int s = (id >> 5) & (SEQ - 1);
    int h = id >> 16;
    float cs = g_cs[(s << 5) + j], sn = g_sn[(s << 5) + j];

    size_t base = (size_t)h * SEQ * HD + (size_t)s * HD;
    float q1 = g_q[base + j], q2 = g_q[base + j + 32];
    g_q[base + j]      = q1 * cs - q2 * sn;
    g_q[base + j + 32] = q2 * cs + q1 * sn;
    float k1v = g_k[base + j], k2v = g_k[base + j + 32];
    g_k[base + j]      = k1v * cs - k2v * sn;
    g_k[base + j + 32] = k2v * cs + k1v * sn;
}

// ---------------------------------------------------------------------------
// k1 split-K: phase 1 partials (16 heads x 8 splits), phase 2 ordered reduce.
// ---------------------------------------------------------------------------
__global__ void __launch_bounds__(256) k1_part_kernel(const float* __restrict__ lod1)
{
    int h = blockIdx.x, sp = blockIdx.y;
    const float* A = g_k + (size_t)h * SEQ * HD;
    __shared__ float As[16][68];
    __shared__ float Bs[16][68];
    int tid = threadIdx.x;
    int tm = tid >> 4, tn = tid & 15;
    float acc[4][4] = {};

    int kbeg = sp * 256, kend = kbeg + 256;
    for (int k0 = kbeg; k0 < kend; k0 += 16) {
        int row = tid >> 2, c4 = (tid & 3) * 4;
        float4 va = *(const float4*)(A + (size_t)row * 2048 + k0 + c4);
        As[c4 + 0][row] = va.x; As[c4 + 1][row] = va.y;
        As[c4 + 2][row] = va.z; As[c4 + 3][row] = va.w;
        float4 vb = *(const float4*)(lod1 + (size_t)row * 2048 + k0 + c4);
        Bs[c4 + 0][row] = vb.x; Bs[c4 + 1][row] = vb.y;
        Bs[c4 + 2][row] = vb.z; Bs[c4 + 3][row] = vb.w;
        __syncthreads();
#pragma unroll
        for (int kk = 0; kk < 16; kk++) {
            float4 a = *(const float4*)&As[kk][tm * 4];
            float4 b = *(const float4*)&Bs[kk][tn * 4];
            float av[4] = {a.x, a.y, a.z, a.w};
            float bv[4] = {b.x, b.y, b.z, b.w};
#pragma unroll
            for (int i = 0; i < 4; i++)
#pragma unroll
                for (int j = 0; j < 4; j++)
                    acc[i][j] += av[i] * bv[j];
        }
        __syncthreads();
    }
    float* outp = g_k1p + ((size_t)sp * NH + h) * 4096;
#pragma unroll
    for (int i = 0; i < 4; i++)
#pragma unroll
        for (int j = 0; j < 4; j++)
            outp[(size_t)(tm * 4 + i) * 64 + tn * 4 + j] = acc[i][j];
}

__global__ void k1_reduce_kernel()
{
    int i = blockIdx.x * blockDim.x + threadIdx.x;
    if (i >= NH * 4096) return;
    float s = 0.f;
#pragma unroll
    for (int sp = 0; sp < 8; sp++)
        s += g_k1p[(size_t)sp * NH * 4096 + i];
    g_k1[i] = s;
}

// ---------------------------------------------------------------------------
// Top-8 block selection -> 64-bit mask per (h, s).
// ---------------------------------------------------------------------------
__global__ void __launch_bounds__(256) select_kernel()
{
    int h = blockIdx.y;
    __shared__ float k1s[64 * 65];
    int tid = threadIdx.x;
    for (int i = tid; i < 64 * 64; i += 256) {
        int t = i >> 6, d = i & 63;
        k1s[t * 65 + d] = g_k1[(size_t)h * 4096 + i];
    }
    __syncthreads();

    int w = tid >> 5, lane = tid & 31;
    int s = blockIdx.x * 8 + w;
    const float* qp = g_q + (size_t)h * SEQ * HD + (size_t)s * HD;
    float2 qpair = *(const float2*)(qp + 2 * lane);

    float a0 = 0.f, a1 = 0.f;
#pragma unroll
    for (int d = 0; d < 64; d++) {
        float qd = __shfl_sync(0xffffffffu, (d & 1) ? qpair.y : qpair.x, d >> 1);
        a0 += qd * k1s[lane * 65 + d];
        a1 += qd * k1s[(lane + 32) * 65 + d];
    }

    int i0 = lane, i1 = lane + 32;
    unsigned long long msk = 0ull;
#pragma unroll
    for (int it = 0; it < 8; it++) {
        float bv; int bi;
        if (a0 > a1 || (a0 == a1 && i0 < i1)) { bv = a0; bi = i0; }
        else                                  { bv = a1; bi = i1; }
#pragma unroll
        for (int off = 16; off; off >>= 1) {
            float ov = __shfl_xor_sync(0xffffffffu, bv, off);
            int   oi = __shfl_xor_sync(0xffffffffu, bi, off);
            if (ov > bv || (ov == bv && oi < bi)) { bv = ov; bi = oi; }
        }
        msk |= 1ull << bi;
        if (bi == i0) a0 = -INFINITY;
        if (bi == i1) a1 = -INFINITY;
    }
    if (lane == 0) g_sel[(size_t)h * SEQ + s] = msk;
}

// ---------------------------------------------------------------------------
// Single-pass flash attention with online softmax (R5, passing).
// ---------------------------------------------------------------------------
#define ATTN_SMEM_BYTES ((32*68 + 64*68 + 64*68 + 64*36) * 4 + 33 * 8)

__global__ void __launch_bounds__(256) attn_kernel()
{
    extern __shared__ float smf[];
    float* qs = smf;                     // 32*68
    float* ks = qs + 32 * 68;            // 64*68
    float* vs = ks + 64 * 68;            // 64*68
    float* ps = vs + 64 * 68;            // 64*36  (ps[j][r])
    unsigned long long* msk = (unsigned long long*)(ps + 64 * 36); // [33]

    int h = blockIdx.y, qt = blockIdx.x;
    int s0 = qt * 32;
    int tid = threadIdx.x;
    const size_t hbase = (size_t)h * SEQ * HD;

#pragma unroll
    for (int i = 0; i < 2; i++) {
        int idx = tid + i * 256;
        int r = idx >> 4, c4 = (idx & 15) * 4;
        *(float4*)&qs[r * 68 + c4] =
            *(const float4*)(g_q + hbase + (size_t)(s0 + r) * HD + c4);
    }
    if (tid < 32) {
        unsigned long long m = g_sel[(size_t)h * SEQ + s0 + tid];
        msk[tid] = m;
        unsigned lo = (unsigned)m, hi = (unsigned)(m >> 32);
#pragma unroll
        for (int off = 16; off; off >>= 1) {
            lo |= __shfl_xor_sync(0xffffffffu, lo, off);
            hi |= __shfl_xor_sync(0xffffffffu, hi, off);
        }
        if (tid == 0) msk[32] = ((unsigned long long)hi << 32) | lo;
    }
    __syncthreads();

    const int wr = tid >> 5, tc = tid & 31;
    const unsigned long long uni = msk[32];
    unsigned long long mrow[4];
#pragma unroll
    for (int i = 0; i < 4; i++) mrow[i] = msk[wr * 4 + i];

    float m_i[4] = {-1e30f, -1e30f, -1e30f, -1e30f};
    float l_i[4] = {};
    float acc[4][2] = {};

    const int ktmax = (s0 + 31) >> 6;
    for (int kt = 0; kt <= ktmax; kt++) {
        bool need = (kt * 64 + 63 >= s0 - 511) || (((uni >> (2 * kt)) & 3ull) != 0);
        if (!need) continue;

        __syncthreads();
#pragma unroll
        for (int i = 0; i < 4; i++) {
            int idx = tid + i * 256;
            int rr = idx >> 4, c4 = (idx & 15) * 4;
            size_t goff = hbase + (size_t)(kt * 64 + rr) * HD + c4;
            *(float4*)&ks[rr * 68 + c4] = *(const float4*)(g_k + goff);
            *(float4*)&vs[rr * 68 + c4] = *(const float4*)(g_v + goff);
        }
        __syncthreads();

        float sc[4][2] = {};
#pragma unroll
        for (int d4 = 0; d4 < 64; d4 += 4) {
            float4 k0 = *(const float4*)&ks[tc * 68 + d4];
            float4 k1 = *(const float4*)&ks[(tc + 32) * 68 + d4];
#pragma unroll
            for (int i = 0; i < 4; i++) {
                float4 qv = *(const float4*)&qs[(wr * 4 + i) * 68 + d4];
                sc[i][0] += qv.x * k0.x + qv.y * k0.y + qv.z * k0.z + qv.w * k0.w;
                sc[i][1] += qv.x * k1.x + qv.y * k1.y + qv.z * k1.z + qv.w * k1.w;
            }
        }

        float pst[4][2];
#pragma unroll
        for (int i = 0; i < 4; i++) {
            int s = s0 + wr * 4 + i;
#pragma unroll
            for (int jj = 0; jj < 2; jj++) {
                int key = kt * 64 + tc + 32 * jj;
                bool sel = (mrow[i] >> (2 * kt + jj)) & 1ull;
                bool ok = (key <= s) && (key >= s - 511 || sel);
                sc[i][jj] = ok ? sc[i][jj] * ATT_SCALE : -1e30f;
            }
            float rmax = fmaxf(sc[i][0], sc[i][1]);
#pragma unroll
            for (int off = 16; off; off >>= 1)
                rmax = fmaxf(rmax, __shfl_xor_sync(0xffffffffu, rmax, off));
            float mnew = fmaxf(m_i[i], rmax);
            float p0 = __expf(sc[i][0] - mnew);
            float p1 = __expf(sc[i][1] - mnew);
            float rs = p0 + p1;
#pragma unroll
            for (int off = 16; off; off >>= 1)
                rs += __shfl_xor_sync(0xffffffffu, rs, off);
            float f = __expf(m_i[i] - mnew);
            l_i[i] = l_i[i] * f + rs;
            m_i[i] = mnew;
            acc[i][0] *= f; acc[i][1] *= f;
            pst[i][0] = p0; pst[i][1] = p1;
        }
        *(float4*)&ps[tc * 36 + wr * 4] =
            make_float4(pst[0][0], pst[1][0], pst[2][0], pst[3][0]);
        *(float4*)&ps[(tc + 32) * 36 + wr * 4] =
            make_float4(pst[0][1], pst[1][1], pst[2][1], pst[3][1]);
        __syncwarp();

#pragma unroll 8
        for (int j = 0; j < 64; j++) {
            float4 pj = *(const float4*)&ps[j * 36 + wr * 4];
            float2 vj = *(const float2*)&vs[j * 68 + tc * 2];
            acc[0][0] += pj.x * vj.x; acc[0][1] += pj.x * vj.y;
            acc[1][0] += pj.y * vj.x; acc[1][1] += pj.y * vj.y;
            acc[2][0] += pj.z * vj.x; acc[2][1] += pj.z * vj.y;
            acc[3][0] += pj.w * vj.x; acc[3][1] += pj.w * vj.y;
        }
    }

#pragma unroll
    for (int i = 0; i < 4; i++) {
        int s = s0 + wr * 4 + i;
        float inv = 1.0f / l_i[i];
        *(float2*)&g_attn[(size_t)s * DM + h * HD + tc * 2] =
            make_float2(acc[i][0] * inv, acc[i][1] * inv);
    }
}

// ---------------------------------------------------------------------------
extern "C" void kernel_launch(void* const* d_in, const int* in_sizes, int n_in,
                              void* d_out, int out_size)
{
    (void)in_sizes; (void)n_in; (void)out_size;
    const float* x    = (const float*)d_in[0];
    const float* W_q  = (const float*)d_in[1];
    const float* W_k  = (const float*)d_in[2];
    const float* W_v  = (const float*)d_in[3];
    const float* W_o  = (const float*)d_in[4];
    const float* lod1 = (const float*)d_in[5];
    float* out = (float*)d_out;

    static int attr_set = 0;
    if (!attr_set) {
        cudaFuncSetAttribute(attn_kernel,
                             cudaFuncAttributeMaxDynamicSharedMemorySize,
                             ATTN_SMEM_BYTES);
        cudaFuncSetAttribute(bf16x6_gemm_kernel,
                             cudaFuncAttributeMaxDynamicSharedMemorySize,
                             GEMM_SMEM_BYTES);
        attr_set = 1;
    }

    rope_tab_kernel<<<(SEQ * 32) / 256, 256>>>();
    bf16x6_gemm_kernel<<<dim3(DM / 128, SEQ / 128, 3), 256, GEMM_SMEM_BYTES>>>(
        x, W_q, W_k, W_v, nullptr, nullptr, 0);
    rope_apply_kernel<<<(NH * SEQ * 32) / 256, 256>>>();
    k1_part_kernel<<<dim3(NH, 8), 256>>>(lod1);
    k1_reduce_kernel<<<(NH * 4096) / 256, 256>>>();
    select_kernel<<<dim3(SEQ / 8, NH), 256>>>();
    attn_kernel<<<dim3(SEQ / 32, NH), 256, ATTN_SMEM_BYTES>>>();
    bf16x6_gemm_kernel<<<dim3(DM / 128, SEQ / 128, 1), 256, GEMM_SMEM_BYTES>>>(
        nullptr, nullptr, nullptr, nullptr, W_o, out, 1);
}